// round 12
// baseline (speedup 1.0000x reference)
#include <cuda_runtime.h>

#define BW    4096
#define HDIM  512
#define QDIM  256
#define ADIM  128
#define CLEN  16
#define G4    2048

#define HS_STRIDE 36          // padded transposed A-tile stride (multiple of 4 for LDS.128)
#define WT_STRIDE 516         // padded W-tile col stride (multiple of 4)
#define WT_BUF    (16*WT_STRIDE)

// persistent LSTM state + precomputed tables (device globals: allocation-free)
__device__ __align__(16) float g_h[BW*HDIM];
__device__ __align__(16) float g_c[BW*HDIM];
__device__ __align__(16) float g_wihT[ADIM*G4];   // W_ih transposed: [a][4H]
__device__ __align__(16) float g_biasg[G4];       // b_ih + b_hh

typedef unsigned long long u64;

__device__ __forceinline__ u64 pk2(float lo, float hi) {
  u64 r; asm("mov.b64 %0, {%1,%2};" : "=l"(r) : "f"(lo), "f"(hi)); return r;
}
__device__ __forceinline__ float2 upk2(u64 v) {
  float2 r; asm("mov.b64 {%0,%1}, %2;" : "=f"(r.x), "=f"(r.y) : "l"(v)); return r;
}
// packed fp32x2 FMA (SASS FFMA2) — 2x fp32 math per issue slot
__device__ __forceinline__ u64 ffma2(u64 a, u64 b, u64 c) {
  u64 d; asm("fma.rn.f32x2 %0, %1, %2, %3;" : "=l"(d) : "l"(a), "l"(b), "l"(c)); return d;
}
__device__ __forceinline__ float sigm(float x)  { return __fdividef(1.0f, 1.0f + __expf(-x)); }
__device__ __forceinline__ float tanh_(float x) { return 1.0f - __fdividef(2.0f, 1.0f + __expf(2.0f*x)); }

// -------- one-time per-launch prep: W_ih transpose + combined bias --------
__global__ void init_misc(const float* __restrict__ Wih,
                          const float* __restrict__ bih,
                          const float* __restrict__ bhh) {
  int idx = blockIdx.x * blockDim.x + threadIdx.x;
  if (idx < ADIM * G4) {
    int a = idx >> 11;          // / 2048
    int n = idx & (G4 - 1);
    g_wihT[idx] = Wih[n * ADIM + a];
  }
  if (idx < G4) g_biasg[idx] = bih[idx] + bhh[idx];
}

// -------- h0 = qr @ Wp^T + bp ; c0 = 0 --------
__global__ __launch_bounds__(256)
void h0_kernel(const float* __restrict__ qr, const float* __restrict__ Wp,
               const float* __restrict__ bp) {
  extern __shared__ float sm[];
  float* qs = sm;                       // [256][HS_STRIDE] transposed qr tile
  float* wt = sm + QDIM * HS_STRIDE;    // [2][16][WT_STRIDE]

  int tid  = threadIdx.x;
  int row0 = blockIdx.x * 32;

  { // stage qr tile transposed: 32 rows x 256 k
    int r4 = tid >> 6;          // 0..3
    int kq = tid & 63;          // float4 index along k
    #pragma unroll
    for (int rr = 0; rr < 8; rr++) {
      int row = r4 + rr * 4;
      float4 v = *(const float4*)&qr[(size_t)(row0 + row) * QDIM + kq * 4];
      qs[(kq*4+0)*HS_STRIDE + row] = v.x;
      qs[(kq*4+1)*HS_STRIDE + row] = v.y;
      qs[(kq*4+2)*HS_STRIDE + row] = v.z;
      qs[(kq*4+3)*HS_STRIDE + row] = v.w;
    }
  }
  __syncthreads();

  int rg = tid >> 5, ct = tid & 31;         // compute mapping
  int lkg = tid & 3, lc = (tid >> 2) & 63;  // W-load mapping

  for (int nc = 0; nc < 4; nc++) {          // 4 chunks of 128 H-cols
    u64 acc[4][2];
    #pragma unroll
    for (int r = 0; r < 4; r++) { acc[r][0] = 0ull; acc[r][1] = 0ull; }

    float4 wv[2];
    #pragma unroll
    for (int cp = 0; cp < 2; cp++) {
      int n = nc*128 + cp*64 + lc;
      wv[cp] = *(const float4*)&Wp[(size_t)n * QDIM + lkg * 4];
    }
    {
      float* wb = wt;
      #pragma unroll
      for (int cp = 0; cp < 2; cp++) {
        int c = cp*64 + lc;
        wb[(lkg*4+0)*WT_STRIDE + c] = wv[cp].x;
        wb[(lkg*4+1)*WT_STRIDE + c] = wv[cp].y;
        wb[(lkg*4+2)*WT_STRIDE + c] = wv[cp].z;
        wb[(lkg*4+3)*WT_STRIDE + c] = wv[cp].w;
      }
    }
    __syncthreads();

    for (int kt = 0; kt < 16; kt++) {       // K=256, 16 tiles of 16
      if (kt < 15) {
        #pragma unroll
        for (int cp = 0; cp < 2; cp++) {
          int n = nc*128 + cp*64 + lc;
          wv[cp] = *(const float4*)&Wp[(size_t)n * QDIM + (kt+1)*16 + lkg*4];
        }
      }
      const float* wb = wt + (kt & 1) * WT_BUF;
      #pragma unroll
      for (int kk = 0; kk < 16; kk++) {
        int k = kt*16 + kk;
        float4 av = *(const float4*)&qs[k*HS_STRIDE + rg*4];
        u64 a0 = pk2(av.x, av.x), a1 = pk2(av.y, av.y);
        u64 a2 = pk2(av.z, av.z), a3 = pk2(av.w, av.w);
        ulonglong2 bv = *(const ulonglong2*)&wb[kk*WT_STRIDE + ct*4];
        acc[0][0] = ffma2(a0, bv.x, acc[0][0]); acc[0][1] = ffma2(a0, bv.y, acc[0][1]);
        acc[1][0] = ffma2(a1, bv.x, acc[1][0]); acc[1][1] = ffma2(a1, bv.y, acc[1][1]);
        acc[2][0] = ffma2(a2, bv.x, acc[2][0]); acc[2][1] = ffma2(a2, bv.y, acc[2][1]);
        acc[3][0] = ffma2(a3, bv.x, acc[3][0]); acc[3][1] = ffma2(a3, bv.y, acc[3][1]);
      }
      if (kt < 15) {
        float* wb2 = wt + ((kt+1) & 1) * WT_BUF;
        #pragma unroll
        for (int cp = 0; cp < 2; cp++) {
          int c = cp*64 + lc;
          wb2[(lkg*4+0)*WT_STRIDE + c] = wv[cp].x;
          wb2[(lkg*4+1)*WT_STRIDE + c] = wv[cp].y;
          wb2[(lkg*4+2)*WT_STRIDE + c] = wv[cp].z;
          wb2[(lkg*4+3)*WT_STRIDE + c] = wv[cp].w;
        }
      }
      __syncthreads();
    }

    int nb = nc*128 + ct*4;
    float4 bpv = *(const float4*)&bp[nb];
    #pragma unroll
    for (int r = 0; r < 4; r++) {
      int row = row0 + rg*4 + r;
      float2 lo = upk2(acc[r][0]), hi = upk2(acc[r][1]);
      *(float4*)&g_h[(size_t)row * HDIM + nb] =
          make_float4(lo.x + bpv.x, lo.y + bpv.y, hi.x + bpv.z, hi.y + bpv.w);
      *(float4*)&g_c[(size_t)row * HDIM + nb] = make_float4(0.f, 0.f, 0.f, 0.f);
    }
  }
}

// -------- one LSTM step: gates GEMM + cell update + logits GEMM, fully fused --------
__global__ __launch_bounds__(256)
void lstm_step(const int* __restrict__ tch, const float* __restrict__ Whh,
               const float* __restrict__ Wo, const float* __restrict__ bo,
               float* __restrict__ out, int t) {
  extern __shared__ float sm[];
  float* hs  = sm;                         // [512][HS_STRIDE] transposed old h
  float* hn  = sm + HDIM * HS_STRIDE;      // [512][HS_STRIDE] transposed new h
  float* wt  = hn + HDIM * HS_STRIDE;      // [2][16][WT_STRIDE]
  int*   chs = (int*)(wt + 2 * WT_BUF);    // [32] teacher-forced input chars

  int tid  = threadIdx.x;
  int row0 = blockIdx.x * 32;

  if (tid < 32) {
    int ch = 0;
    if (t > 0) {
      int v = tch[(row0 + tid) * CLEN + (t - 1)];
      if (v >= 0 && v < ADIM) ch = v;
    }
    chs[tid] = ch;
  }
  { // stage old h transposed: 32 rows x 512 k
    int r2 = tid >> 7, kq = tid & 127;
    #pragma unroll
    for (int rr = 0; rr < 16; rr++) {
      int row = r2 + rr * 2;
      float4 v = *(const float4*)&g_h[(size_t)(row0 + row) * HDIM + kq * 4];
      hs[(kq*4+0)*HS_STRIDE + row] = v.x;
      hs[(kq*4+1)*HS_STRIDE + row] = v.y;
      hs[(kq*4+2)*HS_STRIDE + row] = v.z;
      hs[(kq*4+3)*HS_STRIDE + row] = v.w;
    }
  }
  __syncthreads();

  int rg = tid >> 5, ct = tid & 31;         // 8 row-groups x 32 col-threads
  int lkg = tid & 3, lc = (tid >> 2) & 63;  // W-load mapping

  // ---- gates: 4 chunks of 128 H-cols, all 4 gates computed together ----
  for (int nc = 0; nc < 4; nc++) {
    u64 acc[4][4][2];                       // [row][gate][f32x2 pair]
    #pragma unroll
    for (int r = 0; r < 4; r++)
      #pragma unroll
      for (int g = 0; g < 4; g++) { acc[r][g][0] = 0ull; acc[r][g][1] = 0ull; }

    float4 wv[8];
    #pragma unroll
    for (int g = 0; g < 4; g++)
      #pragma unroll
      for (int cp = 0; cp < 2; cp++) {
        int n = g*512 + nc*128 + cp*64 + lc;
        wv[g*2+cp] = *(const float4*)&Whh[(size_t)n * HDIM + lkg * 4];
      }
    {
      float* wb = wt;
      #pragma unroll
      for (int g = 0; g < 4; g++)
        #pragma unroll
        for (int cp = 0; cp < 2; cp++) {
          float4 v = wv[g*2+cp];
          int c = g*128 + cp*64 + lc;
          wb[(lkg*4+0)*WT_STRIDE + c] = v.x;
          wb[(lkg*4+1)*WT_STRIDE + c] = v.y;
          wb[(lkg*4+2)*WT_STRIDE + c] = v.z;
          wb[(lkg*4+3)*WT_STRIDE + c] = v.w;
        }
    }
    __syncthreads();

    for (int kt = 0; kt < 32; kt++) {       // K=512, 32 tiles of 16
      if (kt < 31) {
        #pragma unroll
        for (int g = 0; g < 4; g++)
          #pragma unroll
          for (int cp = 0; cp < 2; cp++) {
            int n = g*512 + nc*128 + cp*64 + lc;
            wv[g*2+cp] = *(const float4*)&Whh[(size_t)n * HDIM + (kt+1)*16 + lkg*4];
          }
      }
      const float* wb = wt + (kt & 1) * WT_BUF;
      #pragma unroll
      for (int kk = 0; kk < 16; kk++) {
        int k = kt*16 + kk;
        float4 av = *(const float4*)&hs[k*HS_STRIDE + rg*4];
        u64 ar[4] = { pk2(av.x, av.x), pk2(av.y, av.y),
                      pk2(av.z, av.z), pk2(av.w, av.w) };
        #pragma unroll
        for (int g = 0; g < 4; g++) {
          ulonglong2 bv = *(const ulonglong2*)&wb[kk*WT_STRIDE + g*128 + ct*4];
          #pragma unroll
          for (int r = 0; r < 4; r++) {
            acc[r][g][0] = ffma2(ar[r], bv.x, acc[r][g][0]);
            acc[r][g][1] = ffma2(ar[r], bv.y, acc[r][g][1]);
          }
        }
      }
      if (kt < 31) {
        float* wb2 = wt + ((kt+1) & 1) * WT_BUF;
        #pragma unroll
        for (int g = 0; g < 4; g++)
          #pragma unroll
          for (int cp = 0; cp < 2; cp++) {
            float4 v = wv[g*2+cp];
            int c = g*128 + cp*64 + lc;
            wb2[(lkg*4+0)*WT_STRIDE + c] = v.x;
            wb2[(lkg*4+1)*WT_STRIDE + c] = v.y;
            wb2[(lkg*4+2)*WT_STRIDE + c] = v.z;
            wb2[(lkg*4+3)*WT_STRIDE + c] = v.w;
          }
      }
      __syncthreads();
    }

    // ---- LSTM elementwise for this 128-col chunk ----
    int nb = nc*128 + ct*4;
    float4 bg[4];
    #pragma unroll
    for (int g = 0; g < 4; g++) bg[g] = *(const float4*)&g_biasg[g*512 + nb];

    #pragma unroll
    for (int r = 0; r < 4; r++) {
      int lrow = rg*4 + r;
      int row  = row0 + lrow;
      int ch   = chs[lrow];
      float gv[4][4];
      #pragma unroll
      for (int g = 0; g < 4; g++) {
        float4 wih = *(const float4*)&g_wihT[(size_t)ch * G4 + g*512 + nb];
        float2 lo = upk2(acc[r][g][0]), hi = upk2(acc[r][g][1]);
        gv[g][0] = lo.x + bg[g].x + wih.x;
        gv[g][1] = lo.y + bg[g].y + wih.y;
        gv[g][2] = hi.x + bg[g].z + wih.z;
        gv[g][3] = hi.y + bg[g].w + wih.w;
      }
      float4 cold = *(const float4*)&g_c[(size_t)row * HDIM + nb];
      float co[4] = { cold.x, cold.y, cold.z, cold.w };
      float cn[4], hh[4];
      #pragma unroll
      for (int j = 0; j < 4; j++) {
        float c2 = sigm(gv[1][j]) * co[j] + sigm(gv[0][j]) * tanh_(gv[2][j]);
        hh[j] = sigm(gv[3][j]) * tanh_(c2);
        cn[j] = c2;
      }
      *(float4*)&g_c[(size_t)row * HDIM + nb] = make_float4(cn[0], cn[1], cn[2], cn[3]);
      *(float4*)&g_h[(size_t)row * HDIM + nb] = make_float4(hh[0], hh[1], hh[2], hh[3]);
      hn[(nb+0)*HS_STRIDE + lrow] = hh[0];
      hn[(nb+1)*HS_STRIDE + lrow] = hh[1];
      hn[(nb+2)*HS_STRIDE + lrow] = hh[2];
      hn[(nb+3)*HS_STRIDE + lrow] = hh[3];
    }
  }
  __syncthreads();   // all hn writes visible; all wt reads done

  // ---- logits = h_new @ Wo^T + bo ----
  {
    u64 acc[4][2];
    #pragma unroll
    for (int r = 0; r < 4; r++) { acc[r][0] = 0ull; acc[r][1] = 0ull; }

    float4 wv[2];
    #pragma unroll
    for (int cp = 0; cp < 2; cp++)
      wv[cp] = *(const float4*)&Wo[(size_t)(cp*64 + lc) * HDIM + lkg * 4];
    {
      float* wb = wt;
      #pragma unroll
      for (int cp = 0; cp < 2; cp++) {
        int c = cp*64 + lc;
        wb[(lkg*4+0)*WT_STRIDE + c] = wv[cp].x;
        wb[(lkg*4+1)*WT_STRIDE + c] = wv[cp].y;
        wb[(lkg*4+2)*WT_STRIDE + c] = wv[cp].z;
        wb[(lkg*4+3)*WT_STRIDE + c] = wv[cp].w;
      }
    }
    __syncthreads();

    for (int kt = 0; kt < 32; kt++) {
      if (kt < 31) {
        #pragma unroll
        for (int cp = 0; cp < 2; cp++)
          wv[cp] = *(const float4*)&Wo[(size_t)(cp*64 + lc) * HDIM + (kt+1)*16 + lkg*4];
      }
      const float* wb = wt + (kt & 1) * WT_BUF;
      #pragma unroll
      for (int kk = 0; kk < 16; kk++) {
        int k = kt*16 + kk;
        float4 av = *(const float4*)&hn[k*HS_STRIDE + rg*4];
        u64 a0 = pk2(av.x, av.x), a1 = pk2(av.y, av.y);
        u64 a2 = pk2(av.z, av.z), a3 = pk2(av.w, av.w);
        ulonglong2 bv = *(const ulonglong2*)&wb[kk*WT_STRIDE + ct*4];
        acc[0][0] = ffma2(a0, bv.x, acc[0][0]); acc[0][1] = ffma2(a0, bv.y, acc[0][1]);
        acc[1][0] = ffma2(a1, bv.x, acc[1][0]); acc[1][1] = ffma2(a1, bv.y, acc[1][1]);
        acc[2][0] = ffma2(a2, bv.x, acc[2][0]); acc[2][1] = ffma2(a2, bv.y, acc[2][1]);
        acc[3][0] = ffma2(a3, bv.x, acc[3][0]); acc[3][1] = ffma2(a3, bv.y, acc[3][1]);
      }
      if (kt < 31) {
        float* wb2 = wt + ((kt+1) & 1) * WT_BUF;
        #pragma unroll
        for (int cp = 0; cp < 2; cp++) {
          int c = cp*64 + lc;
          wb2[(lkg*4+0)*WT_STRIDE + c] = wv[cp].x;
          wb2[(lkg*4+1)*WT_STRIDE + c] = wv[cp].y;
          wb2[(lkg*4+2)*WT_STRIDE + c] = wv[cp].z;
          wb2[(lkg*4+3)*WT_STRIDE + c] = wv[cp].w;
        }
      }
      __syncthreads();
    }

    float4 bov = *(const float4*)&bo[ct*4];
    #pragma unroll
    for (int r = 0; r < 4; r++) {
      int row = row0 + rg*4 + r;
      float2 lo = upk2(acc[r][0]), hi = upk2(acc[r][1]);
      *(float4*)&out[(size_t)row * (CLEN*ADIM) + t*ADIM + ct*4] =
          make_float4(lo.x + bov.x, lo.y + bov.y, hi.x + bov.z, hi.y + bov.w);
    }
  }
}

extern "C" void kernel_launch(void* const* d_in, const int* in_sizes, int n_in,
                              void* d_out, int out_size) {
  const float* qr  = (const float*)d_in[0];
  const int*   tch = (const int*)  d_in[1];
  const float* Wp  = (const float*)d_in[2];
  const float* bp  = (const float*)d_in[3];
  const float* Wih = (const float*)d_in[4];
  const float* Whh = (const float*)d_in[5];
  const float* bih = (const float*)d_in[6];
  const float* bhh = (const float*)d_in[7];
  const float* Wo  = (const float*)d_in[8];
  const float* bo  = (const float*)d_in[9];
  float* out = (float*)d_out;

  int smem_h0   = (QDIM*HS_STRIDE + 2*WT_BUF) * (int)sizeof(float);
  int smem_step = (2*HDIM*HS_STRIDE + 2*WT_BUF) * (int)sizeof(float) + 32 * (int)sizeof(int);

  cudaFuncSetAttribute(h0_kernel, cudaFuncAttributeMaxDynamicSharedMemorySize, smem_h0);
  cudaFuncSetAttribute(lstm_step, cudaFuncAttributeMaxDynamicSharedMemorySize, smem_step);

  init_misc<<<(ADIM*G4)/256, 256>>>(Wih, bih, bhh);
  h0_kernel<<<BW/32, 256, smem_h0>>>(qr, Wp, bp);
  for (int t = 0; t < CLEN; t++)
    lstm_step<<<BW/32, 256, smem_step>>>(tch, Whh, Wo, bo, out, t);
}